// round 6
// baseline (speedup 1.0000x reference)
#include <cuda_runtime.h>
#include <cuda_bf16.h>
#include <cstdint>
#include <cmath>

// ---------------- problem constants ----------------
#define B_   4
#define T_   4096
#define D_   768
#define N_   256
#define HID_ 200
#define P_   32640         // N*(N-1)/2 = 170 * 192
#define NPAD 208
#define MT   192           // pairs per CTA (12 warps x 16 rows)
#define THREADS 384
#define WSCALE 32.0f       // weight scale into e4m3 range
#define HSCALE 8.0f        // h1 scale into e4m3 range

// ---------------- SMEM layout (stage 2) ----------------
// L1 phase: Bbuf[2][208][144B] + Abuf[2][192][144B]
// L2 phase: Bbuf[2][208][144B] + h1[192][272B] (overlaps A bufs)
#define BB_OFF   0
#define BB_SZ    29952     // 208*144
#define AB_OFF   59904
#define AB_SZ    27648     // 192*144
#define H1_OFF   59904     // h1: 192*272 = 52224 (fits in 2*AB_SZ=55296)
#define EXT_OFF  115200    // iis(768) jjs(768) b2s(832) w3s(832)
#define SMEM_TOTAL 118400
#define SAL1B 144          // L1 A/B row stride bytes (128B data + 16 pad) — ldsm conflict-free
#define SH1B  272          // h1 row stride bytes (256B data + 16 pad) — conflict-free

// ---------------- scratch (device globals) ----------------
__device__ __align__(16) __nv_bfloat16 g_embh[B_ * N_ * D_];
__device__ float g_AB[B_ * N_ * 2 * HID_];     // per-node i-term(+b1) | j-term
__device__ float g_S[B_ * N_ * N_];
__device__ __align__(16) unsigned short g_W1t[NPAD * 384];  // e4m3 pairs, [n][k/2], W1c^T * 32
__device__ __align__(16) unsigned short g_W2t[NPAD * 128];  // e4m3 pairs, [n][k/2], W2^T * 32 (K pad 256)

// ---------------- helpers ----------------
__device__ __forceinline__ uint32_t smem_u32(const void* p) {
    uint32_t a;
    asm("{ .reg .u64 t; cvta.to.shared.u64 t, %1; cvt.u32.u64 %0, t; }" : "=r"(a) : "l"(p));
    return a;
}
__device__ __forceinline__ void cp16(uint32_t s, const void* g) {
    asm volatile("cp.async.cg.shared.global [%0], [%1], 16;"
                 :: "r"(s), "l"(__cvta_generic_to_global(g)));
}
#define CP_COMMIT() asm volatile("cp.async.commit_group;" ::: "memory")
#define CP_WAIT0()  asm volatile("cp.async.wait_group 0;" ::: "memory")

__device__ __forceinline__ void ldsm4(uint32_t& r0, uint32_t& r1, uint32_t& r2, uint32_t& r3,
                                      uint32_t addr) {
    asm volatile("ldmatrix.sync.aligned.m8n8.x4.shared.b16 {%0,%1,%2,%3}, [%4];"
                 : "=r"(r0), "=r"(r1), "=r"(r2), "=r"(r3) : "r"(addr));
}
// fp8 MMA: m16n8k32 e4m3 x e4m3 -> f32
__device__ __forceinline__ void mmaf8(float* c,
        uint32_t a0, uint32_t a1, uint32_t a2, uint32_t a3, uint32_t b0, uint32_t b1) {
    asm volatile("mma.sync.aligned.m16n8k32.row.col.f32.e4m3.e4m3.f32 "
                 "{%0,%1,%2,%3}, {%4,%5,%6,%7}, {%8,%9}, {%0,%1,%2,%3};"
                 : "+f"(c[0]), "+f"(c[1]), "+f"(c[2]), "+f"(c[3])
                 : "r"(a0), "r"(a1), "r"(a2), "r"(a3), "r"(b0), "r"(b1));
}
// pack two f32 into one e4m3 pair (consistent order used on BOTH A and B sides)
__device__ __forceinline__ unsigned short pack_e4m3(float f0, float f1) {
    unsigned short r;
    asm("cvt.rn.satfinite.e4m3x2.f32 %0, %1, %2;" : "=h"(r) : "f"(f1), "f"(f0));
    return r;
}

// ---------------- weight transpose/convert precompute ----------------
__global__ void __launch_bounds__(256) prep_weights(const float* __restrict__ W1,
                                                    const float* __restrict__ W2) {
    int idx = blockIdx.x * 256 + threadIdx.x;
    if (idx < NPAD * 384) {          // W1c^T: [n][k2], k = 2*k2
        int n = idx / 384, k2 = idx - n * 384;
        float v0 = 0.f, v1 = 0.f;
        if (n < HID_) {
            v0 = W1[(size_t)(2 * D_ + 2 * k2)     * HID_ + n] * WSCALE;
            v1 = W1[(size_t)(2 * D_ + 2 * k2 + 1) * HID_ + n] * WSCALE;
        }
        g_W1t[idx] = pack_e4m3(v0, v1);
    }
    if (idx < NPAD * 128) {          // W2^T: [n][k2], k = 2*k2, K padded to 256
        int n = idx >> 7, k2 = idx & 127;
        int k = 2 * k2;
        float v0 = 0.f, v1 = 0.f;
        if (n < HID_ && k < HID_)     v0 = W2[(size_t)k * HID_ + n] * WSCALE;
        if (n < HID_ && k + 1 < HID_) v1 = W2[(size_t)(k + 1) * HID_ + n] * WSCALE;
        g_W2t[idx] = pack_e4m3(v0, v1);
    }
}

// ---------------- Stage 1: gather + per-node W1a/W1b terms (8 rows/block) ----------------
__global__ void __launch_bounds__(256) stage1_kernel(
    const float* __restrict__ event_embed, const int* __restrict__ event_idx,
    const float* __restrict__ W1, const float* __restrict__ b1) {
    __shared__ float e[8][D_];
    int row0 = blockIdx.x * 8;
    int b = row0 >> 8, n0 = row0 & 255;
    for (int rr = 0; rr < 8; rr++) {
        int t = event_idx[b * N_ + n0 + rr];
        const float* src = event_embed + ((size_t)b * T_ + t) * D_;
        __nv_bfloat16* dsth = g_embh + (size_t)(b * N_ + n0 + rr) * D_;
        for (int d = threadIdx.x; d < D_; d += 256) {
            float v = src[d];
            e[rr][d] = v;
            dsth[d] = __float2bfloat16(v);
        }
    }
    __syncthreads();
    for (int h = threadIdx.x; h < 2 * HID_; h += 256) {
        const float* w;
        int col;
        float bias;
        if (h < HID_) { col = h;        w = W1;                     bias = b1[h]; }
        else          { col = h - HID_; w = W1 + (size_t)D_ * HID_; bias = 0.f; }
        float a[8];
        #pragma unroll
        for (int r = 0; r < 8; r++) a[r] = bias;
        #pragma unroll 4
        for (int d = 0; d < D_; d++) {
            float wv = w[(size_t)d * HID_ + col];
            #pragma unroll
            for (int r = 0; r < 8; r++) a[r] = fmaf(e[r][d], wv, a[r]);
        }
        size_t base = (size_t)(b * N_ + n0) * (2 * HID_) + h;
        #pragma unroll
        for (int r = 0; r < 8; r++) g_AB[base + (size_t)r * 2 * HID_] = a[r];
    }
}

// ---------------- Stage 2 device pieces ----------------
// L1 B fill: [208][128B] fp8 per chunk (chunk k0 in fp8 units)
__device__ __forceinline__ void fillB1(uint32_t sb, int bufOff, int k0, int tid) {
    const unsigned short* src = g_W1t;
    for (int it = tid; it < 1664; it += THREADS) {
        int n = it >> 3, u = it & 7;
        cp16(sb + BB_OFF + bufOff + n * SAL1B + u * 16,
             src + (size_t)n * 384 + k0 / 2 + u * 8);
    }
}
// L2 B fill: [208][128B] fp8 per chunk
__device__ __forceinline__ void fillB2(uint32_t sb, int bufOff, int k0, int tid) {
    const unsigned short* src = g_W2t;
    for (int it = tid; it < 1664; it += THREADS) {
        int n = it >> 3, u = it & 7;
        cp16(sb + BB_OFF + bufOff + n * SAL1B + u * 16,
             src + (size_t)n * 128 + k0 / 2 + u * 8);
    }
}
// A fill: fp8 pair products, [192][128B] per chunk
__device__ __forceinline__ void fillA(char* smp, int bufOff,
        const __nv_bfloat16* __restrict__ embB,
        const int* iis, const int* jjs, int k0, int tid) {
    for (int it = tid; it < 1536; it += THREADS) {
        int r = it >> 3, u = it & 7;                     // u: group of 16 fp8 cols
        const __nv_bfloat162* pi = (const __nv_bfloat162*)(embB + (size_t)iis[r] * D_ + k0 + u * 16);
        const __nv_bfloat162* pj = (const __nv_bfloat162*)(embB + (size_t)jjs[r] * D_ + k0 + u * 16);
        unsigned short h[8];
        #pragma unroll
        for (int m = 0; m < 8; m++) {
            float2 fi = __bfloat1622float2(pi[m]);
            float2 fj = __bfloat1622float2(pj[m]);
            h[m] = pack_e4m3(fi.x * fj.x, fi.y * fj.y);
        }
        *(uint4*)(smp + AB_OFF + bufOff + r * SAL1B + u * 16) = *(uint4*)h;
    }
}

// L1 MMA on one K=128-fp8 chunk (4 ksteps of k32)
__device__ __forceinline__ void mmaChunk1(uint32_t sb, int bufA, int bufB,
        int w, int lane, float (&acc)[26][4]) {
    uint32_t grp = lane >> 3, lr = lane & 7;
    uint32_t arow = 16 * w + (grp & 1) * 8 + lr;
    uint32_t akoff = (grp >> 1) * 8;        // b16 units
    uint32_t brow = (grp >> 1) * 8 + lr;
    uint32_t bkoff = (grp & 1) * 8;
    uint32_t abase = sb + AB_OFF + bufA + arow * SAL1B;
    uint32_t bbase = sb + BB_OFF + bufB + brow * SAL1B;
    #pragma unroll
    for (int ks = 0; ks < 4; ks++) {
        int kb = ks * 16;                    // b16 cols per kstep
        uint32_t a0, a1, a2, a3;
        ldsm4(a0, a1, a2, a3, abase + (kb + akoff) * 2);
        #pragma unroll
        for (int i = 0; i < 13; i++) {
            uint32_t b0, b1, b2r, b3r;
            ldsm4(b0, b1, b2r, b3r, bbase + (16 * i) * SAL1B + (kb + bkoff) * 2);
            mmaf8(acc[2 * i],     a0, a1, a2, a3, b0, b1);
            mmaf8(acc[2 * i + 1], a0, a1, a2, a3, b2r, b3r);
        }
    }
}

// L2 MMA: A from h1 smem (stride SH1B); gks0 = first global kstep, ksteps count
__device__ __forceinline__ void mmaChunk2(uint32_t sb, int bufB, int gks0, int ksteps,
        int w, int lane, float (&acc)[26][4]) {
    uint32_t grp = lane >> 3, lr = lane & 7;
    uint32_t arow = 16 * w + (grp & 1) * 8 + lr;
    uint32_t akoff = (grp >> 1) * 8;
    uint32_t brow = (grp >> 1) * 8 + lr;
    uint32_t bkoff = (grp & 1) * 8;
    uint32_t abase = sb + H1_OFF + arow * SH1B;
    uint32_t bbase = sb + BB_OFF + bufB + brow * SAL1B;
    for (int ks = 0; ks < ksteps; ks++) {
        uint32_t a0, a1, a2, a3;
        ldsm4(a0, a1, a2, a3, abase + ((gks0 + ks) * 16 + akoff) * 2);
        #pragma unroll
        for (int i = 0; i < 13; i++) {
            uint32_t b0, b1, b2r, b3r;
            ldsm4(b0, b1, b2r, b3r, bbase + (16 * i) * SAL1B + (ks * 16 + bkoff) * 2);
            mmaf8(acc[2 * i],     a0, a1, a2, a3, b0, b1);
            mmaf8(acc[2 * i + 1], a0, a1, a2, a3, b2r, b3r);
        }
    }
}

// ---------------- Stage 2 kernel ----------------
__global__ void __launch_bounds__(THREADS, 1) stage2_mma(
    const float* __restrict__ b2, const float* __restrict__ W3,
    const float* __restrict__ b3) {
    extern __shared__ char sm[];
    uint32_t sb = smem_u32(sm);
    int tid = threadIdx.x;
    int w = tid >> 5, lane = tid & 31;
    int b = blockIdx.y, p0 = blockIdx.x * MT;

    int* iis = (int*)(sm + EXT_OFF);
    int* jjs = (int*)(sm + EXT_OFF + 768);
    float* b2s = (float*)(sm + EXT_OFF + 1536);
    float* w3s = (float*)(sm + EXT_OFF + 2368);

    if (tid < MT) {
        int p = p0 + tid;
        int i = (int)((1.0 + sqrt(1.0 + 8.0 * (double)p)) * 0.5);
        while (i * (i - 1) / 2 > p) --i;
        while ((i + 1) * i / 2 <= p) ++i;
        iis[tid] = i;
        jjs[tid] = p - i * (i - 1) / 2;
    }
    for (int h = tid; h < NPAD; h += THREADS) {
        b2s[h] = (h < HID_) ? b2[h] : 0.f;
        w3s[h] = (h < HID_) ? W3[h] : 0.f;
    }
    __syncthreads();

    const int e2c = (lane & 3) * 2;
    const int r0 = 16 * w + (lane >> 2), r1 = r0 + 8;
    const __nv_bfloat16* embB = g_embh + (size_t)b * N_ * D_;

    // seed L1 accumulators: WSCALE * (A_i + B_j)  (b1 folded into A-term)
    float acc[26][4];
    {
        const float* Ai0 = g_AB + (size_t)(b * N_ + iis[r0]) * (2 * HID_);
        const float* Bj0 = g_AB + (size_t)(b * N_ + jjs[r0]) * (2 * HID_) + HID_;
        const float* Ai1 = g_AB + (size_t)(b * N_ + iis[r1]) * (2 * HID_);
        const float* Bj1 = g_AB + (size_t)(b * N_ + jjs[r1]) * (2 * HID_) + HID_;
        #pragma unroll
        for (int nt = 0; nt < 26; nt++) {
            int c = 8 * nt + e2c;
            acc[nt][0] = (c     < HID_) ? WSCALE * (Ai0[c]     + Bj0[c])     : 0.f;
            acc[nt][1] = (c + 1 < HID_) ? WSCALE * (Ai0[c + 1] + Bj0[c + 1]) : 0.f;
            acc[nt][2] = (c     < HID_) ? WSCALE * (Ai1[c]     + Bj1[c])     : 0.f;
            acc[nt][3] = (c + 1 < HID_) ? WSCALE * (Ai1[c + 1] + Bj1[c + 1]) : 0.f;
        }
    }

    // ---- Layer 1: 6 chunks of 128 fp8-K, double-buffered ----
    fillB1(sb, 0, 0, tid);
    CP_COMMIT();
    fillA(sm, 0, embB, iis, jjs, 0, tid);
    CP_WAIT0();
    __syncthreads();
    for (int c = 0; c < 6; c++) {
        int nc = c + 1;
        if (nc < 6) {
            fillB1(sb, (nc & 1) * BB_SZ, nc * 128, tid);
            CP_COMMIT();
            fillA(sm, (nc & 1) * AB_SZ, embB, iis, jjs, nc * 128, tid);
        }
        mmaChunk1(sb, (c & 1) * AB_SZ, (c & 1) * BB_SZ, w, lane, acc);
        CP_WAIT0();
        __syncthreads();
    }

    // ---- prefetch L2 B chunk0; relu h1 -> smem fp8; zero h1 pad cols ----
    fillB2(sb, 0, 0, tid);
    CP_COMMIT();
    // h1 pad bytes 208..255 of each row must be zero (avoid fp8 NaN garbage)
    for (int it = tid; it < 576; it += THREADS) {
        int r = it / 3, u = it - r * 3;
        *(uint4*)(sm + H1_OFF + r * SH1B + 208 + u * 16) = make_uint4(0, 0, 0, 0);
    }
    const float inv_h = HSCALE / WSCALE;   // h1_stored = relu(acc) * HSCALE/WSCALE
    #pragma unroll
    for (int nt = 0; nt < 26; nt++) {
        int c = 8 * nt + e2c;
        *(unsigned short*)(sm + H1_OFF + r0 * SH1B + c) =
            pack_e4m3(fmaxf(acc[nt][0], 0.f) * inv_h, fmaxf(acc[nt][1], 0.f) * inv_h);
        *(unsigned short*)(sm + H1_OFF + r1 * SH1B + c) =
            pack_e4m3(fmaxf(acc[nt][2], 0.f) * inv_h, fmaxf(acc[nt][3], 0.f) * inv_h);
        acc[nt][0] = 0.f; acc[nt][1] = 0.f; acc[nt][2] = 0.f; acc[nt][3] = 0.f;
    }
    CP_WAIT0();
    __syncthreads();

    // ---- Layer 2: 2 chunks (ksteps 0-3, 4-6); k >= 208 is zero-padded ----
    fillB2(sb, BB_SZ, 128, tid);
    CP_COMMIT();
    mmaChunk2(sb, 0, 0, 4, w, lane, acc);
    CP_WAIT0();
    __syncthreads();
    mmaChunk2(sb, BB_SZ, 4, 3, w, lane, acc);

    // ---- Layer 3: h2 = acc/(WSCALE*HSCALE) + b2; s = relu(h2) . W3 + b3 ----
    const float inv2 = 1.0f / (WSCALE * HSCALE);
    float s0 = 0.f, s1 = 0.f;
    #pragma unroll
    for (int nt = 0; nt < 26; nt++) {
        int c = 8 * nt + e2c;
        float w0 = w3s[c], w1v = w3s[c + 1];
        float bb0 = b2s[c], bb1 = b2s[c + 1];
        s0 = fmaf(fmaxf(fmaf(acc[nt][0], inv2, bb0), 0.f), w0, s0);
        s0 = fmaf(fmaxf(fmaf(acc[nt][1], inv2, bb1), 0.f), w1v, s0);
        s1 = fmaf(fmaxf(fmaf(acc[nt][2], inv2, bb0), 0.f), w0, s1);
        s1 = fmaf(fmaxf(fmaf(acc[nt][3], inv2, bb1), 0.f), w1v, s1);
    }
    s0 += __shfl_xor_sync(0xffffffffu, s0, 1);
    s0 += __shfl_xor_sync(0xffffffffu, s0, 2);
    s1 += __shfl_xor_sync(0xffffffffu, s1, 1);
    s1 += __shfl_xor_sync(0xffffffffu, s1, 2);
    if ((lane & 3) == 0) {
        float bb3 = b3[0];
        g_S[(size_t)(b * N_ + iis[r0]) * N_ + jjs[r0]] = s0 + bb3;
        g_S[(size_t)(b * N_ + iis[r1]) * N_ + jjs[r1]] = s1 + bb3;
    }
}

// ---------------- Stage 3: masked row softmax ----------------
__global__ void __launch_bounds__(128) softmax_kernel(float* __restrict__ out) {
    int blk = blockIdx.x;
    int i = blk & 255;
    const float* srow = g_S + (size_t)blk * N_;
    float* orow = out + (size_t)blk * N_;
    __shared__ float redm[4], redz[4];
    int tid = threadIdx.x;

    float m = (tid == 0) ? 0.f : -INFINITY;
    for (int j = tid; j < i; j += 128) m = fmaxf(m, srow[j]);
    #pragma unroll
    for (int o = 16; o; o >>= 1) m = fmaxf(m, __shfl_xor_sync(0xffffffffu, m, o));
    if ((tid & 31) == 0) redm[tid >> 5] = m;
    __syncthreads();
    m = fmaxf(fmaxf(redm[0], redm[1]), fmaxf(redm[2], redm[3]));

    float z = (tid == 0) ? expf(-m) : 0.f;
    for (int j = tid; j < i; j += 128) z += expf(srow[j] - m);
    #pragma unroll
    for (int o = 16; o; o >>= 1) z += __shfl_xor_sync(0xffffffffu, z, o);
    if ((tid & 31) == 0) redz[tid >> 5] = z;
    __syncthreads();
    z = redz[0] + redz[1] + redz[2] + redz[3];
    float invz = 1.f / z;

    for (int j = tid; j < N_; j += 128) {
        float o_;
        if (j < i)       o_ = expf(srow[j] - m) * invz;
        else if (j == i) o_ = expf(-m) * invz;
        else             o_ = -1000.0f;
        orow[j] = o_;
    }
}

// ---------------- launch ----------------
extern "C" void kernel_launch(void* const* d_in, const int* in_sizes, int n_in,
                              void* d_out, int out_size) {
    (void)in_sizes; (void)n_in; (void)out_size;
    const float* event_embed = (const float*)d_in[0];
    const int*   event_idx   = (const int*)d_in[1];
    const float* W1 = (const float*)d_in[2];
    const float* b1 = (const float*)d_in[3];
    const float* W2 = (const float*)d_in[4];
    const float* b2 = (const float*)d_in[5];
    const float* W3 = (const float*)d_in[6];
    const float* b3 = (const float*)d_in[7];
    float* out = (float*)d_out;

    cudaFuncSetAttribute(stage2_mma, cudaFuncAttributeMaxDynamicSharedMemorySize, SMEM_TOTAL);

    prep_weights<<<(NPAD * 384 + 255) / 256, 256>>>(W1, W2);
    stage1_kernel<<<B_ * N_ / 8, 256>>>(event_embed, event_idx, W1, b1);

    dim3 grid2(P_ / MT, B_);
    stage2_mma<<<grid2, THREADS, SMEM_TOTAL>>>(b2, W3, b3);

    softmax_kernel<<<B_ * N_, 128>>>(out);
}

// round 7
// speedup vs baseline: 1.0017x; 1.0017x over previous
#include <cuda_runtime.h>
#include <cuda_bf16.h>
#include <cstdint>
#include <cmath>

// ---------------- problem constants ----------------
#define B_   4
#define T_   4096
#define D_   768
#define N_   256
#define HID_ 200
#define P_   32640         // N*(N-1)/2 = 170 * 192
#define NPAD 208
#define MT   192           // pairs per CTA (12 warps x 16 rows)
#define THREADS 384
#define WSCALE 32.0f       // weight scale into e4m3 range
#define HSCALE 8.0f        // h1 scale into e4m3 range

// ---------------- SMEM layout (stage 2) ----------------
// L1 phase: Bbuf[2][208][144B] + Abuf[2][192][144B]
// L2 phase: Bbuf[2][208][144B] + h1[192][272B] (overlaps A bufs)
#define BB_OFF   0
#define BB_SZ    29952     // 208*144
#define AB_OFF   59904
#define AB_SZ    27648     // 192*144
#define H1_OFF   59904     // h1: 192*272 = 52224 (fits in 2*AB_SZ=55296)
#define EXT_OFF  115200    // iis(768) jjs(768) b2s(832) w3s(832)
#define SMEM_TOTAL 118400
#define SAL1B 144          // L1 A/B row stride bytes (128B data + 16 pad) — ldsm conflict-free
#define SH1B  272          // h1 row stride bytes (256B data + 16 pad) — conflict-free

// ---------------- scratch (device globals) ----------------
__device__ __align__(16) __nv_bfloat16 g_embh[B_ * N_ * D_];
__device__ float g_AB[B_ * N_ * 2 * HID_];     // per-node i-term(+b1) | j-term
__device__ float g_S[B_ * N_ * N_];
__device__ __align__(16) unsigned short g_W1t[NPAD * 384];  // e4m3 pairs, [n][k/2], W1c^T * 32
__device__ __align__(16) unsigned short g_W2t[NPAD * 128];  // e4m3 pairs, [n][k/2], W2^T * 32 (K pad 256)

// ---------------- helpers ----------------
__device__ __forceinline__ uint32_t smem_u32(const void* p) {
    uint32_t a;
    asm("{ .reg .u64 t; cvta.to.shared.u64 t, %1; cvt.u32.u64 %0, t; }" : "=r"(a) : "l"(p));
    return a;
}
__device__ __forceinline__ void cp16(uint32_t s, const void* g) {
    asm volatile("cp.async.cg.shared.global [%0], [%1], 16;"
                 :: "r"(s), "l"(__cvta_generic_to_global(g)));
}
#define CP_COMMIT() asm volatile("cp.async.commit_group;" ::: "memory")
#define CP_WAIT0()  asm volatile("cp.async.wait_group 0;" ::: "memory")

__device__ __forceinline__ void ldsm4(uint32_t& r0, uint32_t& r1, uint32_t& r2, uint32_t& r3,
                                      uint32_t addr) {
    asm volatile("ldmatrix.sync.aligned.m8n8.x4.shared.b16 {%0,%1,%2,%3}, [%4];"
                 : "=r"(r0), "=r"(r1), "=r"(r2), "=r"(r3) : "r"(addr));
}
// fp8 MMA: m16n8k32 e4m3 x e4m3 -> f32
__device__ __forceinline__ void mmaf8(float* c,
        uint32_t a0, uint32_t a1, uint32_t a2, uint32_t a3, uint32_t b0, uint32_t b1) {
    asm volatile("mma.sync.aligned.m16n8k32.row.col.f32.e4m3.e4m3.f32 "
                 "{%0,%1,%2,%3}, {%4,%5,%6,%7}, {%8,%9}, {%0,%1,%2,%3};"
                 : "+f"(c[0]), "+f"(c[1]), "+f"(c[2]), "+f"(c[3])
                 : "r"(a0), "r"(a1), "r"(a2), "r"(a3), "r"(b0), "r"(b1));
}
// pack two f32 into one e4m3 pair (consistent order used on BOTH A and B sides)
__device__ __forceinline__ unsigned short pack_e4m3(float f0, float f1) {
    unsigned short r;
    asm("cvt.rn.satfinite.e4m3x2.f32 %0, %1, %2;" : "=h"(r) : "f"(f1), "f"(f0));
    return r;
}

// ---------------- weight transpose/convert precompute ----------------
__global__ void __launch_bounds__(256) prep_weights(const float* __restrict__ W1,
                                                    const float* __restrict__ W2) {
    int idx = blockIdx.x * 256 + threadIdx.x;
    if (idx < NPAD * 384) {          // W1c^T: [n][k2], k = 2*k2
        int n = idx / 384, k2 = idx - n * 384;
        float v0 = 0.f, v1 = 0.f;
        if (n < HID_) {
            v0 = W1[(size_t)(2 * D_ + 2 * k2)     * HID_ + n] * WSCALE;
            v1 = W1[(size_t)(2 * D_ + 2 * k2 + 1) * HID_ + n] * WSCALE;
        }
        g_W1t[idx] = pack_e4m3(v0, v1);
    }
    if (idx < NPAD * 128) {          // W2^T: [n][k2], k = 2*k2, K padded to 256
        int n = idx >> 7, k2 = idx & 127;
        int k = 2 * k2;
        float v0 = 0.f, v1 = 0.f;
        if (n < HID_ && k < HID_)     v0 = W2[(size_t)k * HID_ + n] * WSCALE;
        if (n < HID_ && k + 1 < HID_) v1 = W2[(size_t)(k + 1) * HID_ + n] * WSCALE;
        g_W2t[idx] = pack_e4m3(v0, v1);
    }
}

// ---------------- Stage 1: gather + per-node W1a/W1b terms (8 rows/block) ----------------
__global__ void __launch_bounds__(256) stage1_kernel(
    const float* __restrict__ event_embed, const int* __restrict__ event_idx,
    const float* __restrict__ W1, const float* __restrict__ b1) {
    __shared__ float e[8][D_];
    int row0 = blockIdx.x * 8;
    int b = row0 >> 8, n0 = row0 & 255;
    for (int rr = 0; rr < 8; rr++) {
        int t = event_idx[b * N_ + n0 + rr];
        const float* src = event_embed + ((size_t)b * T_ + t) * D_;
        __nv_bfloat16* dsth = g_embh + (size_t)(b * N_ + n0 + rr) * D_;
        for (int d = threadIdx.x; d < D_; d += 256) {
            float v = src[d];
            e[rr][d] = v;
            dsth[d] = __float2bfloat16(v);
        }
    }
    __syncthreads();
    for (int h = threadIdx.x; h < 2 * HID_; h += 256) {
        const float* w;
        int col;
        float bias;
        if (h < HID_) { col = h;        w = W1;                     bias = b1[h]; }
        else          { col = h - HID_; w = W1 + (size_t)D_ * HID_; bias = 0.f; }
        float a[8];
        #pragma unroll
        for (int r = 0; r < 8; r++) a[r] = bias;
        #pragma unroll 4
        for (int d = 0; d < D_; d++) {
            float wv = w[(size_t)d * HID_ + col];
            #pragma unroll
            for (int r = 0; r < 8; r++) a[r] = fmaf(e[r][d], wv, a[r]);
        }
        size_t base = (size_t)(b * N_ + n0) * (2 * HID_) + h;
        #pragma unroll
        for (int r = 0; r < 8; r++) g_AB[base + (size_t)r * 2 * HID_] = a[r];
    }
}

// ---------------- Stage 2 device pieces ----------------
// L1 B fill: [208][128B] fp8 per chunk (chunk k0 in fp8 units)
__device__ __forceinline__ void fillB1(uint32_t sb, int bufOff, int k0, int tid) {
    const unsigned short* src = g_W1t;
    for (int it = tid; it < 1664; it += THREADS) {
        int n = it >> 3, u = it & 7;
        cp16(sb + BB_OFF + bufOff + n * SAL1B + u * 16,
             src + (size_t)n * 384 + k0 / 2 + u * 8);
    }
}
// L2 B fill: [208][128B] fp8 per chunk
__device__ __forceinline__ void fillB2(uint32_t sb, int bufOff, int k0, int tid) {
    const unsigned short* src = g_W2t;
    for (int it = tid; it < 1664; it += THREADS) {
        int n = it >> 3, u = it & 7;
        cp16(sb + BB_OFF + bufOff + n * SAL1B + u * 16,
             src + (size_t)n * 128 + k0 / 2 + u * 8);
    }
}
// A fill: fp8 pair products, [192][128B] per chunk
__device__ __forceinline__ void fillA(char* smp, int bufOff,
        const __nv_bfloat16* __restrict__ embB,
        const int* iis, const int* jjs, int k0, int tid) {
    for (int it = tid; it < 1536; it += THREADS) {
        int r = it >> 3, u = it & 7;                     // u: group of 16 fp8 cols
        const __nv_bfloat162* pi = (const __nv_bfloat162*)(embB + (size_t)iis[r] * D_ + k0 + u * 16);
        const __nv_bfloat162* pj = (const __nv_bfloat162*)(embB + (size_t)jjs[r] * D_ + k0 + u * 16);
        unsigned short h[8];
        #pragma unroll
        for (int m = 0; m < 8; m++) {
            float2 fi = __bfloat1622float2(pi[m]);
            float2 fj = __bfloat1622float2(pj[m]);
            h[m] = pack_e4m3(fi.x * fj.x, fi.y * fj.y);
        }
        *(uint4*)(smp + AB_OFF + bufOff + r * SAL1B + u * 16) = *(uint4*)h;
    }
}

// L1 MMA on one K=128-fp8 chunk (4 ksteps of k32)
__device__ __forceinline__ void mmaChunk1(uint32_t sb, int bufA, int bufB,
        int w, int lane, float (&acc)[26][4]) {
    uint32_t grp = lane >> 3, lr = lane & 7;
    uint32_t arow = 16 * w + (grp & 1) * 8 + lr;
    uint32_t akoff = (grp >> 1) * 8;        // b16 units
    uint32_t brow = (grp >> 1) * 8 + lr;
    uint32_t bkoff = (grp & 1) * 8;
    uint32_t abase = sb + AB_OFF + bufA + arow * SAL1B;
    uint32_t bbase = sb + BB_OFF + bufB + brow * SAL1B;
    #pragma unroll
    for (int ks = 0; ks < 4; ks++) {
        int kb = ks * 16;                    // b16 cols per kstep
        uint32_t a0, a1, a2, a3;
        ldsm4(a0, a1, a2, a3, abase + (kb + akoff) * 2);
        #pragma unroll
        for (int i = 0; i < 13; i++) {
            uint32_t b0, b1, b2r, b3r;
            ldsm4(b0, b1, b2r, b3r, bbase + (16 * i) * SAL1B + (kb + bkoff) * 2);
            mmaf8(acc[2 * i],     a0, a1, a2, a3, b0, b1);
            mmaf8(acc[2 * i + 1], a0, a1, a2, a3, b2r, b3r);
        }
    }
}

// L2 MMA: A from h1 smem (stride SH1B); gks0 = first global kstep, ksteps count
__device__ __forceinline__ void mmaChunk2(uint32_t sb, int bufB, int gks0, int ksteps,
        int w, int lane, float (&acc)[26][4]) {
    uint32_t grp = lane >> 3, lr = lane & 7;
    uint32_t arow = 16 * w + (grp & 1) * 8 + lr;
    uint32_t akoff = (grp >> 1) * 8;
    uint32_t brow = (grp >> 1) * 8 + lr;
    uint32_t bkoff = (grp & 1) * 8;
    uint32_t abase = sb + H1_OFF + arow * SH1B;
    uint32_t bbase = sb + BB_OFF + bufB + brow * SAL1B;
    for (int ks = 0; ks < ksteps; ks++) {
        uint32_t a0, a1, a2, a3;
        ldsm4(a0, a1, a2, a3, abase + ((gks0 + ks) * 16 + akoff) * 2);
        #pragma unroll
        for (int i = 0; i < 13; i++) {
            uint32_t b0, b1, b2r, b3r;
            ldsm4(b0, b1, b2r, b3r, bbase + (16 * i) * SAL1B + (ks * 16 + bkoff) * 2);
            mmaf8(acc[2 * i],     a0, a1, a2, a3, b0, b1);
            mmaf8(acc[2 * i + 1], a0, a1, a2, a3, b2r, b3r);
        }
    }
}

// ---------------- Stage 2 kernel ----------------
__global__ void __launch_bounds__(THREADS, 1) stage2_mma(
    const float* __restrict__ b2, const float* __restrict__ W3,
    const float* __restrict__ b3) {
    extern __shared__ char sm[];
    uint32_t sb = smem_u32(sm);
    int tid = threadIdx.x;
    int w = tid >> 5, lane = tid & 31;
    int b = blockIdx.y, p0 = blockIdx.x * MT;

    int* iis = (int*)(sm + EXT_OFF);
    int* jjs = (int*)(sm + EXT_OFF + 768);
    float* b2s = (float*)(sm + EXT_OFF + 1536);
    float* w3s = (float*)(sm + EXT_OFF + 2368);

    if (tid < MT) {
        int p = p0 + tid;
        int i = (int)((1.0 + sqrt(1.0 + 8.0 * (double)p)) * 0.5);
        while (i * (i - 1) / 2 > p) --i;
        while ((i + 1) * i / 2 <= p) ++i;
        iis[tid] = i;
        jjs[tid] = p - i * (i - 1) / 2;
    }
    for (int h = tid; h < NPAD; h += THREADS) {
        b2s[h] = (h < HID_) ? b2[h] : 0.f;
        w3s[h] = (h < HID_) ? W3[h] : 0.f;
    }
    __syncthreads();

    const int e2c = (lane & 3) * 2;
    const int r0 = 16 * w + (lane >> 2), r1 = r0 + 8;
    const __nv_bfloat16* embB = g_embh + (size_t)b * N_ * D_;

    // seed L1 accumulators: WSCALE * (A_i + B_j)  (b1 folded into A-term)
    float acc[26][4];
    {
        const float* Ai0 = g_AB + (size_t)(b * N_ + iis[r0]) * (2 * HID_);
        const float* Bj0 = g_AB + (size_t)(b * N_ + jjs[r0]) * (2 * HID_) + HID_;
        const float* Ai1 = g_AB + (size_t)(b * N_ + iis[r1]) * (2 * HID_);
        const float* Bj1 = g_AB + (size_t)(b * N_ + jjs[r1]) * (2 * HID_) + HID_;
        #pragma unroll
        for (int nt = 0; nt < 26; nt++) {
            int c = 8 * nt + e2c;
            acc[nt][0] = (c     < HID_) ? WSCALE * (Ai0[c]     + Bj0[c])     : 0.f;
            acc[nt][1] = (c + 1 < HID_) ? WSCALE * (Ai0[c + 1] + Bj0[c + 1]) : 0.f;
            acc[nt][2] = (c     < HID_) ? WSCALE * (Ai1[c]     + Bj1[c])     : 0.f;
            acc[nt][3] = (c + 1 < HID_) ? WSCALE * (Ai1[c + 1] + Bj1[c + 1]) : 0.f;
        }
    }

    // ---- Layer 1: 6 chunks of 128 fp8-K, double-buffered ----
    fillB1(sb, 0, 0, tid);
    CP_COMMIT();
    fillA(sm, 0, embB, iis, jjs, 0, tid);
    CP_WAIT0();
    __syncthreads();
    for (int c = 0; c < 6; c++) {
        int nc = c + 1;
        if (nc < 6) {
            fillB1(sb, (nc & 1) * BB_SZ, nc * 128, tid);
            CP_COMMIT();
            fillA(sm, (nc & 1) * AB_SZ, embB, iis, jjs, nc * 128, tid);
        }
        mmaChunk1(sb, (c & 1) * AB_SZ, (c & 1) * BB_SZ, w, lane, acc);
        CP_WAIT0();
        __syncthreads();
    }

    // ---- prefetch L2 B chunk0; relu h1 -> smem fp8; zero h1 pad cols ----
    fillB2(sb, 0, 0, tid);
    CP_COMMIT();
    // h1 pad bytes 208..255 of each row must be zero (avoid fp8 NaN garbage)
    for (int it = tid; it < 576; it += THREADS) {
        int r = it / 3, u = it - r * 3;
        *(uint4*)(sm + H1_OFF + r * SH1B + 208 + u * 16) = make_uint4(0, 0, 0, 0);
    }
    const float inv_h = HSCALE / WSCALE;   // h1_stored = relu(acc) * HSCALE/WSCALE
    #pragma unroll
    for (int nt = 0; nt < 26; nt++) {
        int c = 8 * nt + e2c;
        *(unsigned short*)(sm + H1_OFF + r0 * SH1B + c) =
            pack_e4m3(fmaxf(acc[nt][0], 0.f) * inv_h, fmaxf(acc[nt][1], 0.f) * inv_h);
        *(unsigned short*)(sm + H1_OFF + r1 * SH1B + c) =
            pack_e4m3(fmaxf(acc[nt][2], 0.f) * inv_h, fmaxf(acc[nt][3], 0.f) * inv_h);
        acc[nt][0] = 0.f; acc[nt][1] = 0.f; acc[nt][2] = 0.f; acc[nt][3] = 0.f;
    }
    CP_WAIT0();
    __syncthreads();

    // ---- Layer 2: 2 chunks (ksteps 0-3, 4-6); k >= 208 is zero-padded ----
    fillB2(sb, BB_SZ, 128, tid);
    CP_COMMIT();
    mmaChunk2(sb, 0, 0, 4, w, lane, acc);
    CP_WAIT0();
    __syncthreads();
    mmaChunk2(sb, BB_SZ, 4, 3, w, lane, acc);

    // ---- Layer 3: h2 = acc/(WSCALE*HSCALE) + b2; s = relu(h2) . W3 + b3 ----
    const float inv2 = 1.0f / (WSCALE * HSCALE);
    float s0 = 0.f, s1 = 0.f;
    #pragma unroll
    for (int nt = 0; nt < 26; nt++) {
        int c = 8 * nt + e2c;
        float w0 = w3s[c], w1v = w3s[c + 1];
        float bb0 = b2s[c], bb1 = b2s[c + 1];
        s0 = fmaf(fmaxf(fmaf(acc[nt][0], inv2, bb0), 0.f), w0, s0);
        s0 = fmaf(fmaxf(fmaf(acc[nt][1], inv2, bb1), 0.f), w1v, s0);
        s1 = fmaf(fmaxf(fmaf(acc[nt][2], inv2, bb0), 0.f), w0, s1);
        s1 = fmaf(fmaxf(fmaf(acc[nt][3], inv2, bb1), 0.f), w1v, s1);
    }
    s0 += __shfl_xor_sync(0xffffffffu, s0, 1);
    s0 += __shfl_xor_sync(0xffffffffu, s0, 2);
    s1 += __shfl_xor_sync(0xffffffffu, s1, 1);
    s1 += __shfl_xor_sync(0xffffffffu, s1, 2);
    if ((lane & 3) == 0) {
        float bb3 = b3[0];
        g_S[(size_t)(b * N_ + iis[r0]) * N_ + jjs[r0]] = s0 + bb3;
        g_S[(size_t)(b * N_ + iis[r1]) * N_ + jjs[r1]] = s1 + bb3;
    }
}

// ---------------- Stage 3: masked row softmax ----------------
__global__ void __launch_bounds__(128) softmax_kernel(float* __restrict__ out) {
    int blk = blockIdx.x;
    int i = blk & 255;
    const float* srow = g_S + (size_t)blk * N_;
    float* orow = out + (size_t)blk * N_;
    __shared__ float redm[4], redz[4];
    int tid = threadIdx.x;

    float m = (tid == 0) ? 0.f : -INFINITY;
    for (int j = tid; j < i; j += 128) m = fmaxf(m, srow[j]);
    #pragma unroll
    for (int o = 16; o; o >>= 1) m = fmaxf(m, __shfl_xor_sync(0xffffffffu, m, o));
    if ((tid & 31) == 0) redm[tid >> 5] = m;
    __syncthreads();
    m = fmaxf(fmaxf(redm[0], redm[1]), fmaxf(redm[2], redm[3]));

    float z = (tid == 0) ? expf(-m) : 0.f;
    for (int j = tid; j < i; j += 128) z += expf(srow[j] - m);
    #pragma unroll
    for (int o = 16; o; o >>= 1) z += __shfl_xor_sync(0xffffffffu, z, o);
    if ((tid & 31) == 0) redz[tid >> 5] = z;
    __syncthreads();
    z = redz[0] + redz[1] + redz[2] + redz[3];
    float invz = 1.f / z;

    for (int j = tid; j < N_; j += 128) {
        float o_;
        if (j < i)       o_ = expf(srow[j] - m) * invz;
        else if (j == i) o_ = expf(-m) * invz;
        else             o_ = -1000.0f;
        orow[j] = o_;
    }
}

// ---------------- launch ----------------
extern "C" void kernel_launch(void* const* d_in, const int* in_sizes, int n_in,
                              void* d_out, int out_size) {
    (void)in_sizes; (void)n_in; (void)out_size;
    const float* event_embed = (const float*)d_in[0];
    const int*   event_idx   = (const int*)d_in[1];
    const float* W1 = (const float*)d_in[2];
    const float* b1 = (const float*)d_in[3];
    const float* W2 = (const float*)d_in[4];
    const float* b2 = (const float*)d_in[5];
    const float* W3 = (const float*)d_in[6];
    const float* b3 = (const float*)d_in[7];
    float* out = (float*)d_out;

    cudaFuncSetAttribute(stage2_mma, cudaFuncAttributeMaxDynamicSharedMemorySize, SMEM_TOTAL);

    prep_weights<<<(NPAD * 384 + 255) / 256, 256>>>(W1, W2);
    stage1_kernel<<<B_ * N_ / 8, 256>>>(event_embed, event_idx, W1, b1);

    dim3 grid2(P_ / MT, B_);
    stage2_mma<<<grid2, THREADS, SMEM_TOTAL>>>(b2, W3, b3);

    softmax_kernel<<<B_ * N_, 128>>>(out);
}